// round 13
// baseline (speedup 1.0000x reference)
#include <cuda_runtime.h>
#include <cuda_bf16.h>

// SingleLIFLayer: V <- V + (dt/tau)*(V_reset - V + I); spike = V >= V_th; reset.
// T=1024 steps x N=65536 neurons. Irreducible traffic: 256 MB R + 256 MB W.
//
// V9 = V8 (no split, 1024x64, TBATCH=32 double buffer, __ldcs/__stcs)
//  + FULL 1:1 interleave: each consume step issues exactly one prefetch load
//    of the next batch -> perfectly uniform per-warp read stream (R12 showed
//    finer interleave = more DRAM%: burst->half gave 92.0->88.5).
//  + shorter V chain: V' = 0.95*V + (0.05*I) with the product off-chain
//    (FFMA+FSET+FFMA = 12 cyc/step vs 16). 1-ulp rounding delta vs reference;
//    nearest threshold approach ~0.04 -> decisions exact (rel_err 0.0 all rounds).

#define LIF_T   1024
#define LIF_N   65536
#define THREADS 64
#define TBATCH  32
#define NBATCH  (LIF_T / TBATCH)   // 32

__global__ __launch_bounds__(THREADS, 6)
void lif_kernel(const float* __restrict__ in, float* __restrict__ out) {
    const int n = blockIdx.x * THREADS + threadIdx.x;   // neuron index
    const float alpha = 0.05f;     // dt/tau
    const float decay = 0.95f;     // 1 - alpha (exact in fp32? 0.95 rounds; ok)
    const float vth   = 1.0f;

    float V = 0.0f;   // V_reset = 0

    const float* __restrict__ ip = in  + n;
    float*       __restrict__ sp = out + n;

    float bufA[TBATCH];
    float bufB[TBATCH];

    // Prologue: batch 0 into A.
    #pragma unroll
    for (int k = 0; k < TBATCH; ++k)
        bufA[k] = __ldcs(ip + k * LIF_N);

    #pragma unroll 1
    for (int tb = 0; tb < NBATCH; tb += 2) {
        // ---- consume A, prefetch B, 1:1 interleaved ----
        {
            const float* ipn = ip + (tb + 1) * (TBATCH * LIF_N);
            float* spb = sp + tb * (TBATCH * LIF_N);
            const bool pf = (tb + 1 < NBATCH);
            #pragma unroll
            for (int k = 0; k < TBATCH; ++k) {
                if (pf) bufB[k] = __ldcs(ipn + k * LIF_N);
                float c = alpha * bufA[k];          // off-chain FMUL
                V = fmaf(decay, V, c);              // chain: FFMA
                float s = (V >= vth) ? 1.0f : 0.0f; // chain: FSET (data)
                __stcs(spb + k * LIF_N, s);
                V = fmaf(-s, V, V);                 // chain: FFMA (exact reset)
            }
        }
        // ---- consume B, prefetch A, 1:1 interleaved ----
        {
            const float* ipn = ip + (tb + 2) * (TBATCH * LIF_N);
            float* spb = sp + (tb + 1) * (TBATCH * LIF_N);
            const bool pf = (tb + 2 < NBATCH);
            #pragma unroll
            for (int k = 0; k < TBATCH; ++k) {
                if (pf) bufA[k] = __ldcs(ipn + k * LIF_N);
                float c = alpha * bufB[k];
                V = fmaf(decay, V, c);
                float s = (V >= vth) ? 1.0f : 0.0f;
                __stcs(spb + k * LIF_N, s);
                V = fmaf(-s, V, V);
            }
        }
    }
}

extern "C" void kernel_launch(void* const* d_in, const int* in_sizes, int n_in,
                              void* d_out, int out_size) {
    const float* input = (const float*)d_in[0];
    float* spikes = (float*)d_out;

    const int grid = LIF_N / THREADS;   // 1024 CTAs x 64 threads = 65536 threads
    lif_kernel<<<grid, THREADS>>>(input, spikes);
}

// round 14
// speedup vs baseline: 1.0200x; 1.0200x over previous
#include <cuda_runtime.h>
#include <cuda_bf16.h>

// SingleLIFLayer: V <- V + (dt/tau)*(V_reset - V + I); spike = V >= V_th; reset.
// T=1024 steps x N=65536 neurons. Irreducible traffic: 256 MB R + 256 MB W.
//
// V10 = V8 (the 88.5us winner: no split, 1024x64, TBATCH=32 double buffer,
//       HALF=16 burst-interleaved prefetch, __ldcs/__stcs) with ONE change:
//       shorter serial V chain. V' = 0.95*V + (0.05*I), the product off-chain
//       (hoistable to load arrival) -> chain FFMA+FSET+FFMA = 12 cyc/step
//       vs 16. Interleave grain stays 16: R7/R12/R13 measured 32/16/1-grain
//       at 92.0/88.5/89.9 us -> 16 is the MLP-vs-smoothness optimum.
// Numerics: 1-ulp vs reference; nearest threshold approach ~0.04; this exact
// form already passed with rel_err 0.0 in R13.

#define LIF_T   1024
#define LIF_N   65536
#define THREADS 64
#define TBATCH  32
#define HALF    16
#define NBATCH  (LIF_T / TBATCH)   // 32

__device__ __forceinline__ void consume_half(const float* __restrict__ cur,
                                             float& V, float* __restrict__ spb) {
    const float alpha = 0.05f;
    const float decay = 0.95f;
    const float vth   = 1.0f;
    #pragma unroll
    for (int k = 0; k < HALF; ++k) {
        float c = alpha * cur[k];             // off-chain FMUL (hoistable)
        V = fmaf(decay, V, c);                // chain: FFMA
        float s = (V >= vth) ? 1.0f : 0.0f;   // chain: FSET (data, no pred-guard)
        __stcs(spb + k * LIF_N, s);
        V = fmaf(-s, V, V);                   // chain: FFMA (s==1 -> exactly 0)
    }
}

__global__ __launch_bounds__(THREADS, 6)
void lif_kernel(const float* __restrict__ in, float* __restrict__ out) {
    const int n = blockIdx.x * THREADS + threadIdx.x;   // neuron index

    float V = 0.0f;   // V_reset = 0

    const float* __restrict__ ip = in  + n;
    float*       __restrict__ sp = out + n;

    float bufA[TBATCH];
    float bufB[TBATCH];

    // Prologue: batch 0 into A.
    #pragma unroll
    for (int k = 0; k < TBATCH; ++k)
        bufA[k] = __ldcs(ip + k * LIF_N);

    #pragma unroll 1
    for (int tb = 0; tb < NBATCH; tb += 2) {
        // ---- consume A, prefetch B (16-burst interleaved) ----
        {
            const float* ipn = ip + (tb + 1) * (TBATCH * LIF_N);
            float* spb = sp + tb * (TBATCH * LIF_N);
            const bool pf = (tb + 1 < NBATCH);

            if (pf) {
                #pragma unroll
                for (int k = 0; k < HALF; ++k)
                    bufB[k] = __ldcs(ipn + k * LIF_N);
            }
            consume_half(bufA, V, spb);

            if (pf) {
                #pragma unroll
                for (int k = HALF; k < TBATCH; ++k)
                    bufB[k] = __ldcs(ipn + k * LIF_N);
            }
            consume_half(bufA + HALF, V, spb + HALF * LIF_N);
        }
        // ---- consume B, prefetch A (16-burst interleaved) ----
        {
            const float* ipn = ip + (tb + 2) * (TBATCH * LIF_N);
            float* spb = sp + (tb + 1) * (TBATCH * LIF_N);
            const bool pf = (tb + 2 < NBATCH);

            if (pf) {
                #pragma unroll
                for (int k = 0; k < HALF; ++k)
                    bufA[k] = __ldcs(ipn + k * LIF_N);
            }
            consume_half(bufB, V, spb);

            if (pf) {
                #pragma unroll
                for (int k = HALF; k < TBATCH; ++k)
                    bufA[k] = __ldcs(ipn + k * LIF_N);
            }
            consume_half(bufB + HALF, V, spb + HALF * LIF_N);
        }
    }
}

extern "C" void kernel_launch(void* const* d_in, const int* in_sizes, int n_in,
                              void* d_out, int out_size) {
    const float* input = (const float*)d_in[0];
    float* spikes = (float*)d_out;

    const int grid = LIF_N / THREADS;   // 1024 CTAs x 64 threads = 65536 threads
    lif_kernel<<<grid, THREADS>>>(input, spikes);
}